// round 4
// baseline (speedup 1.0000x reference)
#include <cuda_runtime.h>
#include <cuda_bf16.h>
#include <cstdint>
#include <cstddef>

#define TLEN  512
#define BATCH 128
#define EDIM  128
#define HDIM  128
#define GDIM  512   // 4*H

// Scratch (device globals — no allocation)
static __device__ float g_xp[(size_t)2 * TLEN * BATCH * GDIM];   // [dir][t][b][4H] = 256MB
static __device__ float g_pool[2 * BATCH * HDIM];

// ---------- f32x2 helpers ----------
__device__ __forceinline__ unsigned long long pk2(float lo, float hi) {
    unsigned long long r;
    asm("mov.b64 %0, {%1, %2};" : "=l"(r) : "f"(lo), "f"(hi));
    return r;
}
__device__ __forceinline__ void upk2(unsigned long long v, float& lo, float& hi) {
    asm("mov.b64 {%0, %1}, %2;" : "=f"(lo), "=f"(hi) : "l"(v));
}
__device__ __forceinline__ unsigned long long ffma2(unsigned long long a,
                                                    unsigned long long b,
                                                    unsigned long long c) {
    unsigned long long d;
    asm("fma.rn.f32x2 %0, %1, %2, %3;" : "=l"(d) : "l"(a), "l"(b), "l"(c));
    return d;
}
__device__ __forceinline__ float sig_fast(float x)  { return __fdividef(1.f, 1.f + __expf(-x)); }
__device__ __forceinline__ float tanh_fast(float x) {
    float e = __expf(-2.f * x);
    return __fdividef(1.f - e, 1.f + e);
}

// =====================================================================
// Kernel 1: embedding gather + input projection (both dirs).
// xp[dir][t][b][g] = emb[b, tsrc] . Wih[g] + bih[g] + bhh[g]
// Tile 128(b) x 128(g), K=128. grid=(4 gate tiles, 2*512), 256 thr, 8x8 micro.
// =====================================================================
#define SA 132
#define PROJ_SMEM (2 * 128 * SA * 4)

__global__ void __launch_bounds__(256) proj_kernel(
    const int* __restrict__ x, const float* __restrict__ table,
    const float* __restrict__ Wih_f, const float* __restrict__ bih_f, const float* __restrict__ bhh_f,
    const float* __restrict__ Wih_b, const float* __restrict__ bih_b, const float* __restrict__ bhh_b)
{
    extern __shared__ float sm[];
    float* As = sm;               // [128][SA] gathered embedding rows
    float* Bs = sm + 128 * SA;    // [128][SA] Wih rows
    __shared__ int   tok_s[128];
    __shared__ float bias_s[128];

    const int tid   = threadIdx.x;
    const int gtile = blockIdx.x;        // 0..3
    const int dir   = blockIdx.y >> 9;
    const int t     = blockIdx.y & 511;

    const float* Wih = dir ? Wih_b : Wih_f;
    const float* bi  = dir ? bih_b : bih_f;
    const float* bh  = dir ? bhh_b : bhh_f;
    const int tsrc   = dir ? (TLEN - 1 - t) : t;

    if (tid < 128) {
        tok_s[tid] = x[tid * TLEN + tsrc];
        const int gg = gtile * 128 + tid;
        bias_s[tid] = bi[gg] + bh[gg];
    }
    __syncthreads();

    #pragma unroll
    for (int it = 0; it < 16; ++it) {
        const int c = it * 256 + tid;
        const int i = c >> 5, kc = (c & 31) << 2;
        *(float4*)&As[i * SA + kc] = *(const float4*)&table[(size_t)tok_s[i] * EDIM + kc];
    }
    #pragma unroll
    for (int it = 0; it < 16; ++it) {
        const int c = it * 256 + tid;
        const int j = c >> 5, kc = (c & 31) << 2;
        *(float4*)&Bs[j * SA + kc] = *(const float4*)&Wih[(size_t)(gtile * 128 + j) * EDIM + kc];
    }
    __syncthreads();

    const int ty = tid >> 4, tx = tid & 15;
    unsigned long long acc[8][8];
    #pragma unroll
    for (int r = 0; r < 8; ++r)
        #pragma unroll
        for (int j = 0; j < 8; ++j) acc[r][j] = 0ull;

    #pragma unroll 2
    for (int k4 = 0; k4 < 32; ++k4) {
        ulonglong2 bv[8];
        #pragma unroll
        for (int j = 0; j < 8; ++j)
            bv[j] = *(const ulonglong2*)&Bs[(j * 16 + tx) * SA + k4 * 4];
        #pragma unroll
        for (int r = 0; r < 8; ++r) {
            const ulonglong2 av = *(const ulonglong2*)&As[(ty * 8 + r) * SA + k4 * 4];
            #pragma unroll
            for (int j = 0; j < 8; ++j) {
                acc[r][j] = ffma2(av.x, bv[j].x, acc[r][j]);
                acc[r][j] = ffma2(av.y, bv[j].y, acc[r][j]);
            }
        }
    }

    float* outp = g_xp + (size_t)(dir * TLEN + t) * BATCH * GDIM + gtile * 128;
    #pragma unroll
    for (int r = 0; r < 8; ++r) {
        const int b = ty * 8 + r;
        #pragma unroll
        for (int j = 0; j < 8; ++j) {
            float lo, hi; upk2(acc[r][j], lo, hi);
            const int jj = j * 16 + tx;
            outp[(size_t)b * GDIM + jj] = lo + hi + bias_s[jj];
        }
    }
}

// =====================================================================
// Kernel 2: persistent LSTM scan. 128 CTAs = (dir, batch-pair); 512 thr.
// Thread g holds Whh row g as 64 bf16x2 regs; computes preact for 2 batch
// rows/step with fma.rn.f32x2; 256 threads do the (c,h) update. 2 bars/step.
// =====================================================================
__global__ void __launch_bounds__(512) scan_kernel(
    const float* __restrict__ Whh_f, const float* __restrict__ Whh_b)
{
    __shared__ __align__(16) float h_s[2][HDIM];
    __shared__ float gact[2][GDIM];

    const int g   = threadIdx.x;
    const int dir = blockIdx.x >> 6;
    const int b0  = (blockIdx.x & 63) * 2;
    const float* Whh = dir ? Whh_b : Whh_f;

    unsigned wv[64];
    const float2* wrow = (const float2*)(Whh + (size_t)g * HDIM);
    #pragma unroll
    for (int q = 0; q < 64; ++q) {
        const float2 w = __ldg(&wrow[q]);
        const unsigned lo = (unsigned)__bfloat16_as_ushort(__float2bfloat16(w.x));
        const unsigned hi = (unsigned)__bfloat16_as_ushort(__float2bfloat16(w.y));
        wv[q] = (hi << 16) | lo;
    }

    if (g < 256) h_s[g >> 7][g & 127] = 0.f;
    float c_st = 0.f;
    float hmax = -3.4e38f;

    const float* xp = g_xp + (size_t)dir * TLEN * BATCH * GDIM;
    float x0 = __ldg(&xp[(size_t)b0 * GDIM + g]);
    float x1 = __ldg(&xp[(size_t)(b0 + 1) * GDIM + g]);
    __syncthreads();

    const int gate_type = g >> 7;   // 0:i 1:f 2:g 3:o

    for (int t = 0; t < TLEN; ++t) {
        const float cx0 = x0, cx1 = x1;
        const int tn = (t + 1 < TLEN) ? t + 1 : t;
        x0 = __ldg(&xp[((size_t)tn * BATCH + b0) * GDIM + g]);
        x1 = __ldg(&xp[((size_t)tn * BATCH + b0 + 1) * GDIM + g]);

        unsigned long long a0 = pk2(cx0, 0.f), c0 = 0ull;
        unsigned long long a1 = pk2(cx1, 0.f), c1 = 0ull;
        const ulonglong2* h40 = (const ulonglong2*)h_s[0];
        const ulonglong2* h41 = (const ulonglong2*)h_s[1];
        #pragma unroll
        for (int p = 0; p < 16; ++p) {   // 8 k per iter
            const unsigned u0 = wv[4*p+0], u1 = wv[4*p+1], u2 = wv[4*p+2], u3 = wv[4*p+3];
            const unsigned long long w0 = pk2(__uint_as_float(u0 << 16), __uint_as_float(u0 & 0xffff0000u));
            const unsigned long long w1 = pk2(__uint_as_float(u1 << 16), __uint_as_float(u1 & 0xffff0000u));
            const unsigned long long w2 = pk2(__uint_as_float(u2 << 16), __uint_as_float(u2 & 0xffff0000u));
            const unsigned long long w3 = pk2(__uint_as_float(u3 << 16), __uint_as_float(u3 & 0xffff0000u));
            const ulonglong2 hA = h40[2*p], hB = h40[2*p+1];
            a0 = ffma2(w0, hA.x, a0);  c0 = ffma2(w1, hA.y, c0);
            a0 = ffma2(w2, hB.x, a0);  c0 = ffma2(w3, hB.y, c0);
            const ulonglong2 hC = h41[2*p], hD = h41[2*p+1];
            a1 = ffma2(w0, hC.x, a1);  c1 = ffma2(w1, hC.y, c1);
            a1 = ffma2(w2, hD.x, a1);  c1 = ffma2(w3, hD.y, c1);
        }
        float lo, hi;
        upk2(a0, lo, hi); float s0 = lo + hi;
        upk2(c0, lo, hi); s0 += lo + hi;
        upk2(a1, lo, hi); float s1 = lo + hi;
        upk2(c1, lo, hi); s1 += lo + hi;

        float v0, v1;
        if (gate_type == 2) { v0 = tanh_fast(s0); v1 = tanh_fast(s1); }
        else                { v0 = sig_fast(s0);  v1 = sig_fast(s1); }
        gact[0][g] = v0;
        gact[1][g] = v1;
        __syncthreads();

        if (g < 256) {
            const int bb = g >> 7, u = g & 127;
            const float iv = gact[bb][u];
            const float fv = gact[bb][128 + u];
            const float gv = gact[bb][256 + u];
            const float ov = gact[bb][384 + u];
            c_st = fv * c_st + iv * gv;
            const float hn = ov * tanh_fast(c_st);
            hmax = fmaxf(hmax, hn);
            h_s[bb][u] = hn;
        }
        __syncthreads();
    }

    if (g < 256) {
        const int bb = g >> 7, u = g & 127;
        g_pool[((size_t)dir * BATCH + b0 + bb) * HDIM + u] = hmax;
    }
}

// =====================================================================
// Kernel 3: MLP head. grid=128 (batch), 64 threads (hidden units).
// =====================================================================
__global__ void __launch_bounds__(64) mlp_kernel(
    const float* __restrict__ W1, const float* __restrict__ b1,
    const float* __restrict__ W2, const float* __restrict__ b2,
    float* __restrict__ out)
{
    __shared__ __align__(16) float pv[256];
    __shared__ float red[64];
    const int b = blockIdx.x;
    const int j = threadIdx.x;

    for (int k = j; k < 256; k += 64) {
        const int dir = k >> 7, u = k & 127;
        pv[k] = g_pool[((size_t)dir * BATCH + b) * HDIM + u];
    }
    __syncthreads();

    float acc = b1[j];
    const float4* w4 = (const float4*)(W1 + (size_t)j * 256);
    const float4* p4 = (const float4*)pv;
    #pragma unroll 8
    for (int k = 0; k < 64; ++k) {
        const float4 w = w4[k], p = p4[k];
        acc += w.x * p.x + w.y * p.y + w.z * p.z + w.w * p.w;
    }
    red[j] = fmaxf(acc, 0.f) * W2[j];
    __syncthreads();

    if (j == 0) {
        float s = b2[0];
        #pragma unroll
        for (int k = 0; k < 64; ++k) s += red[k];
        out[b] = 1.f / (1.f + expf(-s));
    }
}

// =====================================================================
extern "C" void kernel_launch(void* const* d_in, const int* in_sizes, int n_in,
                              void* d_out, int out_size) {
    const int*   x     = (const int*)d_in[0];
    const float* table = (const float*)d_in[1];
    const float* Wih_f = (const float*)d_in[2];
    const float* Whh_f = (const float*)d_in[3];
    const float* bih_f = (const float*)d_in[4];
    const float* bhh_f = (const float*)d_in[5];
    const float* Wih_b = (const float*)d_in[6];
    const float* Whh_b = (const float*)d_in[7];
    const float* bih_b = (const float*)d_in[8];
    const float* bhh_b = (const float*)d_in[9];
    const float* W1    = (const float*)d_in[10];
    const float* b1    = (const float*)d_in[11];
    const float* W2    = (const float*)d_in[12];
    const float* b2    = (const float*)d_in[13];
    float* out = (float*)d_out;

    cudaFuncSetAttribute(proj_kernel, cudaFuncAttributeMaxDynamicSharedMemorySize, PROJ_SMEM);

    dim3 pg(4, 2 * TLEN);
    proj_kernel<<<pg, 256, PROJ_SMEM>>>(x, table, Wih_f, bih_f, bhh_f, Wih_b, bih_b, bhh_b);
    scan_kernel<<<128, 512>>>(Whh_f, Whh_b);
    mlp_kernel<<<128, 64>>>(W1, b1, W2, b2, out);
}